// round 14
// baseline (speedup 1.0000x reference)
#include <cuda_runtime.h>
#include <cuda_fp16.h>
#include <cstdint>
#include <math.h>

#define Mdim 8192
#define Hdim 768
#define BM 128
#define BN 64
#define BK 32
#define RSW 20          // smem row stride in 32-bit words (40 halves)
#define NKT (Hdim / BK) // 24
#define PST1 4          // L1 pipeline depth
#define PST2 3          // L2 dual pipeline depth
#define NTILE_X (Hdim / BN)   // 12
#define NTILE_Y (Mdim / BM)   // 64
#define NTILES (NTILE_X * NTILE_Y)  // 768
#define PGRID2 296      // persistent grid: 2 CTAs/SM * 148

// ---------------- scratch (static device globals; no allocation) ----------------
__device__ __half g_ah[Mdim * Hdim];     // fp16 modal_a
__device__ __half g_wh[4][Hdim * Hdim];  // fp16 W1m, W1v, W2m, W2v
__device__ __half g_hm[Mdim * Hdim];     // fp16 tanh(layer1m)
__device__ __half g_hv[Mdim * Hdim];     // fp16 tanh(layer1v)
__device__ float g_colpart[5][NTILE_Y][Hdim];  // Smu, Smu2, Siv, Smiv, Smmiv
__device__ float g_negcol[Hdim];
__device__ float g_part[NTILES];         // per-tile pos partials
__device__ int g_ctr[4];                 // work-stealing counters

// ---------------------------- helpers -------------------------------------------
__device__ __forceinline__ uint32_t smem_u32(const void* p) {
    uint32_t a;
    asm("{ .reg .u64 t; cvta.to.shared.u64 t, %1; cvt.u32.u64 %0, t; }"
        : "=r"(a) : "l"(p));
    return a;
}
__device__ __forceinline__ float tanh_fast(float x) {
    float y;
    asm("tanh.approx.f32 %0, %1;" : "=f"(y) : "f"(x));
    return y;
}
#define LDSM_X4(r0, r1, r2, r3, addr) \
    asm volatile("ldmatrix.sync.aligned.m8n8.x4.shared.b16 {%0,%1,%2,%3}, [%4];" \
        : "=r"(r0), "=r"(r1), "=r"(r2), "=r"(r3) : "r"(addr))
#define MMA16816(c0, c1, c2, c3, a0, a1, a2, a3, b0, b1) \
    asm volatile( \
        "mma.sync.aligned.m16n8k16.row.col.f32.f16.f16.f32 " \
        "{%0,%1,%2,%3}, {%4,%5,%6,%7}, {%8,%9}, {%0,%1,%2,%3};" \
        : "+f"(c0), "+f"(c1), "+f"(c2), "+f"(c3) \
        : "r"(a0), "r"(a1), "r"(a2), "r"(a3), "r"(b0), "r"(b1))

// -------------------- pack: modal_a + all 4 weights, one launch ------------------
__global__ __launch_bounds__(256) void pack_all(
    const float* __restrict__ a,
    const float* __restrict__ w0, const float* __restrict__ w1,
    const float* __restrict__ w2, const float* __restrict__ w3,
    __half* __restrict__ ah, __half* __restrict__ wh) {
    if (blockIdx.x == 0 && threadIdx.x < 4) g_ctr[threadIdx.x] = 0;  // reset schedulers
    const int na = Mdim * Hdim / 8;
    const int nw = Hdim * Hdim / 8;
    const int total = na + 4 * nw;
    for (int i = blockIdx.x * 256 + threadIdx.x; i < total; i += gridDim.x * 256) {
        const float* src;
        __half* dst;
        int idx;
        if (i < na) { src = a; dst = ah; idx = i; }
        else {
            int r = i - na;
            int wsel = r / nw;
            idx = r - wsel * nw;
            src = (wsel == 0) ? w0 : (wsel == 1) ? w1 : (wsel == 2) ? w2 : w3;
            dst = wh + (size_t)wsel * Hdim * Hdim;
        }
        float4 v0 = ((const float4*)src)[idx * 2];
        float4 v1 = ((const float4*)src)[idx * 2 + 1];
        __half2 h0 = __floats2half2_rn(v0.x, v0.y);
        __half2 h1 = __floats2half2_rn(v0.z, v0.w);
        __half2 h2 = __floats2half2_rn(v1.x, v1.y);
        __half2 h3 = __floats2half2_rn(v1.z, v1.w);
        *(uint4*)(dst + (size_t)idx * 8) =
            make_uint4(*(uint32_t*)&h0, *(uint32_t*)&h1,
                       *(uint32_t*)&h2, *(uint32_t*)&h3);
    }
}

// ---------------- layer-1 dual-branch GEMM: one A tile, two B tiles --------------
__global__ __launch_bounds__(256, 2) void gemm_l1(
    const __half* __restrict__ A,
    const __half* __restrict__ W0, const __half* __restrict__ W1,
    const float* __restrict__ bias0, const float* __restrict__ bias1,
    __half* __restrict__ H0, __half* __restrict__ H1)
{
    extern __shared__ uint32_t sm[];
    __shared__ int s_tile;
    const uint32_t sA = smem_u32(sm);
    const uint32_t sB0 = sA + PST1 * BM * RSW * 4;
    const uint32_t sB1 = sB0 + PST1 * BN * RSW * 4;

    const int tid = threadIdx.x;
    const int wid = tid >> 5, lane = tid & 31;
    const int g = lane >> 2, tg = lane & 3;
    const int wm0 = (wid & 3) * 32;
    const int wn0 = (wid >> 2) * 32;

    const int lrow = tid >> 2;
    const int lc = tid & 3;
    const uint32_t dab = sA + (uint32_t)(lrow * RSW + lc * 4) * 4;
    const uint32_t db0 = sB0 + (uint32_t)(lrow * RSW + lc * 4) * 4;
    const uint32_t db1 = sB1 + (uint32_t)(lrow * RSW + lc * 4) * 4;
    const uint32_t rowstep = 64 * RSW * 4;
    const uint32_t abufstep = BM * RSW * 4;
    const uint32_t bbufstep = BN * RSW * 4;

    const int mi = lane >> 3, mr = lane & 7;
    uint32_t aoff[2];
#pragma unroll
    for (int t = 0; t < 2; t++)
        aoff[t] = (uint32_t)(((wm0 + t * 16 + (mi & 1) * 8 + mr) * RSW + (mi >> 1) * 4) * 4);
    uint32_t boff[2];
#pragma unroll
    for (int jp = 0; jp < 2; jp++)
        boff[jp] = (uint32_t)(((wn0 + (jp * 2 + (mi >> 1)) * 8 + mr) * RSW + (mi & 1) * 4) * 4);

    while (true) {
        if (tid == 0) s_tile = atomicAdd(&g_ctr[0], 1);
        __syncthreads();
        const int tile = s_tile;
        if (tile >= NTILES) break;

        const int by = tile / NTILE_X;
        const int bx = tile - by * NTILE_X;
        const int m0 = by * BM;
        const int n0 = bx * BN;

        const __half* agb = A + (size_t)(m0 + lrow) * Hdim + lc * 8;
        const __half* b0gb = W0 + (size_t)(n0 + lrow) * Hdim + lc * 8;
        const __half* b1gb = W1 + (size_t)(n0 + lrow) * Hdim + lc * 8;

        float c[2][2][4][4];
#pragma unroll
        for (int br = 0; br < 2; br++)
#pragma unroll
            for (int t = 0; t < 2; t++)
#pragma unroll
                for (int j = 0; j < 4; j++)
#pragma unroll
                    for (int q = 0; q < 4; q++) c[br][t][j][q] = 0.0f;

#define PREFETCH(kt) do { \
    const __half* _ag = agb + (kt) * BK; \
    uint32_t _da = dab + ((kt) % PST1) * abufstep; \
    asm volatile("cp.async.cg.shared.global [%0], [%1], 16;" \
        :: "r"(_da), "l"(_ag) : "memory"); \
    asm volatile("cp.async.cg.shared.global [%0], [%1], 16;" \
        :: "r"(_da + rowstep), "l"(_ag + (size_t)64 * Hdim) : "memory"); \
    asm volatile("cp.async.cg.shared.global [%0], [%1], 16;" \
        :: "r"(db0 + ((kt) % PST1) * bbufstep), "l"(b0gb + (kt) * BK) : "memory"); \
    asm volatile("cp.async.cg.shared.global [%0], [%1], 16;" \
        :: "r"(db1 + ((kt) % PST1) * bbufstep), "l"(b1gb + (kt) * BK) : "memory"); \
    asm volatile("cp.async.commit_group;" ::: "memory"); \
} while (0)

        PREFETCH(0);
        PREFETCH(1);
        PREFETCH(2);

        for (int kt = 0; kt < NKT; kt++) {
            asm volatile("cp.async.wait_group 2;" ::: "memory");
            __syncthreads();

            if (kt + 3 < NKT) PREFETCH(kt + 3);
            else asm volatile("cp.async.commit_group;" ::: "memory");

            const uint32_t stA = sA + (kt % PST1) * abufstep;
            const uint32_t stB0 = sB0 + (kt % PST1) * bbufstep;
            const uint32_t stB1 = sB1 + (kt % PST1) * bbufstep;
#pragma unroll
            for (int ks = 0; ks < 2; ks++) {
                const uint32_t ko = ks * 32;
                uint32_t a[2][4];
#pragma unroll
                for (int t = 0; t < 2; t++)
                    LDSM_X4(a[t][0], a[t][1], a[t][2], a[t][3], stA + aoff[t] + ko);
#pragma unroll
                for (int jp = 0; jp < 2; jp++) {
                    uint32_t b[4];
                    LDSM_X4(b[0], b[1], b[2], b[3], stB0 + boff[jp] + ko);
#pragma unroll
                    for (int t = 0; t < 2; t++) {
                        MMA16816(c[0][t][jp*2][0], c[0][t][jp*2][1], c[0][t][jp*2][2], c[0][t][jp*2][3],
                                 a[t][0], a[t][1], a[t][2], a[t][3], b[0], b[1]);
                        MMA16816(c[0][t][jp*2+1][0], c[0][t][jp*2+1][1], c[0][t][jp*2+1][2], c[0][t][jp*2+1][3],
                                 a[t][0], a[t][1], a[t][2], a[t][3], b[2], b[3]);
                    }
                }
#pragma unroll
                for (int jp = 0; jp < 2; jp++) {
                    uint32_t b[4];
                    LDSM_X4(b[0], b[1], b[2], b[3], stB1 + boff[jp] + ko);
#pragma unroll
                    for (int t = 0; t < 2; t++) {
                        MMA16816(c[1][t][jp*2][0], c[1][t][jp*2][1], c[1][t][jp*2][2], c[1][t][jp*2][3],
                                 a[t][0], a[t][1], a[t][2], a[t][3], b[0], b[1]);
                        MMA16816(c[1][t][jp*2+1][0], c[1][t][jp*2+1][1], c[1][t][jp*2+1][2], c[1][t][jp*2+1][3],
                                 a[t][0], a[t][1], a[t][2], a[t][3], b[2], b[3]);
                    }
                }
            }
        }
#undef PREFETCH

#pragma unroll
        for (int br = 0; br < 2; br++) {
            const float* bias = br ? bias1 : bias0;
            __half* Ch = br ? H1 : H0;
#pragma unroll
            for (int j = 0; j < 4; j++) {
                const int ncol = n0 + wn0 + j * 8 + tg * 2;
                const float bv0 = bias[ncol];
                const float bv1 = bias[ncol + 1];
#pragma unroll
                for (int t = 0; t < 2; t++) {
#pragma unroll
                    for (int h = 0; h < 2; h++) {
                        const int row = m0 + wm0 + t * 16 + g + h * 8;
                        float v0 = c[br][t][j][h * 2 + 0] + bv0;
                        float v1 = c[br][t][j][h * 2 + 1] + bv1;
                        __half2 hv = __floats2half2_rn(tanh_fast(v0), tanh_fast(v1));
                        *(__half2*)&Ch[(size_t)row * Hdim + ncol] = hv;
                    }
                }
            }
        }
        __syncthreads();
    }
}

// ------------- layer-2 dual GEMM: mu & v per tile + fused loss statistics --------
// Per tile: mu = Am@Wm^T+bm, v = Av@Wv^T+bv, iv = exp(-tanh(v)).
// Emits per-tile pos partial and per-(by,col) sums {mu, mu^2, iv, mu*iv, mu^2*iv}.
__global__ __launch_bounds__(256, 2) void gemm_l2dual(
    const __half* __restrict__ Am, const __half* __restrict__ Av,
    const __half* __restrict__ Wm, const __half* __restrict__ Wv,
    const float* __restrict__ biasm, const float* __restrict__ biasv,
    const float* __restrict__ modal_b)
{
    extern __shared__ uint32_t sm[];
    __shared__ int s_tile;
    const uint32_t sA0 = smem_u32(sm);
    const uint32_t sA1 = sA0 + PST2 * BM * RSW * 4;
    const uint32_t sB0 = sA1 + PST2 * BM * RSW * 4;
    const uint32_t sB1 = sB0 + PST2 * BN * RSW * 4;

    const int tid = threadIdx.x;
    const int wid = tid >> 5, lane = tid & 31;
    const int g = lane >> 2, tg = lane & 3;
    const int wm0 = (wid & 3) * 32;
    const int wn0 = (wid >> 2) * 32;

    const int lrow = tid >> 2;          // 0..63
    const int lc = tid & 3;
    const uint32_t da0 = sA0 + (uint32_t)(lrow * RSW + lc * 4) * 4;
    const uint32_t da1 = sA1 + (uint32_t)(lrow * RSW + lc * 4) * 4;
    const uint32_t db0 = sB0 + (uint32_t)(lrow * RSW + lc * 4) * 4;
    const uint32_t db1 = sB1 + (uint32_t)(lrow * RSW + lc * 4) * 4;
    const uint32_t rowstep = 64 * RSW * 4;
    const uint32_t abufstep = BM * RSW * 4;
    const uint32_t bbufstep = BN * RSW * 4;

    const int mi = lane >> 3, mr = lane & 7;
    uint32_t aoff[2];
#pragma unroll
    for (int t = 0; t < 2; t++)
        aoff[t] = (uint32_t)(((wm0 + t * 16 + (mi & 1) * 8 + mr) * RSW + (mi >> 1) * 4) * 4);
    uint32_t boff[2];
#pragma unroll
    for (int jp = 0; jp < 2; jp++)
        boff[jp] = (uint32_t)(((wn0 + (jp * 2 + (mi >> 1)) * 8 + mr) * RSW + (mi & 1) * 4) * 4);

    float* sOv = (float*)sm;   // overlay: [5][4 m-warps][64 cols] + [256] pos
    float* sP = sOv + 5 * 256;

    while (true) {
        if (tid == 0) s_tile = atomicAdd(&g_ctr[1], 1);
        __syncthreads();
        const int tile = s_tile;
        if (tile >= NTILES) break;

        const int by = tile / NTILE_X;
        const int bx = tile - by * NTILE_X;
        const int m0 = by * BM;
        const int n0 = bx * BN;

        const __half* a0gb = Am + (size_t)(m0 + lrow) * Hdim + lc * 8;
        const __half* a1gb = Av + (size_t)(m0 + lrow) * Hdim + lc * 8;
        const __half* b0gb = Wm + (size_t)(n0 + lrow) * Hdim + lc * 8;
        const __half* b1gb = Wv + (size_t)(n0 + lrow) * Hdim + lc * 8;

        float c[2][2][4][4];   // [branch: 0=mu 1=v][t][j][q]
#pragma unroll
        for (int br = 0; br < 2; br++)
#pragma unroll
            for (int t = 0; t < 2; t++)
#pragma unroll
                for (int j = 0; j < 4; j++)
#pragma unroll
                    for (int q = 0; q < 4; q++) c[br][t][j][q] = 0.0f;

#define PREFETCH(kt) do { \
    uint32_t _s = ((kt) % PST2); \
    asm volatile("cp.async.cg.shared.global [%0], [%1], 16;" \
        :: "r"(da0 + _s * abufstep), "l"(a0gb + (kt) * BK) : "memory"); \
    asm volatile("cp.async.cg.shared.global [%0], [%1], 16;" \
        :: "r"(da0 + _s * abufstep + rowstep), "l"(a0gb + (kt) * BK + (size_t)64 * Hdim) : "memory"); \
    asm volatile("cp.async.cg.shared.global [%0], [%1], 16;" \
        :: "r"(da1 + _s * abufstep), "l"(a1gb + (kt) * BK) : "memory"); \
    asm volatile("cp.async.cg.shared.global [%0], [%1], 16;" \
        :: "r"(da1 + _s * abufstep + rowstep), "l"(a1gb + (kt) * BK + (size_t)64 * Hdim) : "memory"); \
    asm volatile("cp.async.cg.shared.global [%0], [%1], 16;" \
        :: "r"(db0 + _s * bbufstep), "l"(b0gb + (kt) * BK) : "memory"); \
    asm volatile("cp.async.cg.shared.global [%0], [%1], 16;" \
        :: "r"(db1 + _s * bbufstep), "l"(b1gb + (kt) * BK) : "memory"); \
    asm volatile("cp.async.commit_group;" ::: "memory"); \
} while (0)

        PREFETCH(0);
        PREFETCH(1);

        for (int kt = 0; kt < NKT; kt++) {
            asm volatile("cp.async.wait_group 1;" ::: "memory");
            __syncthreads();

            if (kt + 2 < NKT) PREFETCH(kt + 2);
            else asm volatile("cp.async.commit_group;" ::: "memory");

            const uint32_t stA0 = sA0 + (kt % PST2) * abufstep;
            const uint32_t stA1 = sA1 + (kt % PST2) * abufstep;
            const uint32_t stB0 = sB0 + (kt % PST2) * bbufstep;
            const uint32_t stB1 = sB1 + (kt % PST2) * bbufstep;
#pragma unroll
            for (int ks = 0; ks < 2; ks++) {
                const uint32_t ko = ks * 32;
                uint32_t a0[2][4], a1[2][4];
#pragma unroll
                for (int t = 0; t < 2; t++) {
                    LDSM_X4(a0[t][0], a0[t][1], a0[t][2], a0[t][3], stA0 + aoff[t] + ko);
                    LDSM_X4(a1[t][0], a1[t][1], a1[t][2], a1[t][3], stA1 + aoff[t] + ko);
                }
#pragma unroll
                for (int jp = 0; jp < 2; jp++) {
                    uint32_t b[4];
                    LDSM_X4(b[0], b[1], b[2], b[3], stB0 + boff[jp] + ko);
#pragma unroll
                    for (int t = 0; t < 2; t++) {
                        MMA16816(c[0][t][jp*2][0], c[0][t][jp*2][1], c[0][t][jp*2][2], c[0][t][jp*2][3],
                                 a0[t][0], a0[t][1], a0[t][2], a0[t][3], b[0], b[1]);
                        MMA16816(c[0][t][jp*2+1][0], c[0][t][jp*2+1][1], c[0][t][jp*2+1][2], c[0][t][jp*2+1][3],
                                 a0[t][0], a0[t][1], a0[t][2], a0[t][3], b[2], b[3]);
                    }
                }
#pragma unroll
                for (int jp = 0; jp < 2; jp++) {
                    uint32_t b[4];
                    LDSM_X4(b[0], b[1], b[2], b[3], stB1 + boff[jp] + ko);
#pragma unroll
                    for (int t = 0; t < 2; t++) {
                        MMA16816(c[1][t][jp*2][0], c[1][t][jp*2][1], c[1][t][jp*2][2], c[1][t][jp*2][3],
                                 a1[t][0], a1[t][1], a1[t][2], a1[t][3], b[0], b[1]);
                        MMA16816(c[1][t][jp*2+1][0], c[1][t][jp*2+1][1], c[1][t][jp*2+1][2], c[1][t][jp*2+1][3],
                                 a1[t][0], a1[t][1], a1[t][2], a1[t][3], b[2], b[3]);
                    }
                }
            }
        }
#undef PREFETCH

        // -------- fused loss epilogue --------
        // stage-0 smem (overlay region) is free: all warps passed the kt=NKT-1
        // top barrier, so its last use (kt=NKT-3) is complete.
        float accp = 0.0f;
#pragma unroll
        for (int j = 0; j < 4; j++) {
            const int ncol = n0 + wn0 + j * 8 + tg * 2;
            const float bm0 = biasm[ncol], bm1 = biasm[ncol + 1];
            const float bb0 = biasv[ncol], bb1 = biasv[ncol + 1];
            float smu0 = 0.f, smu20 = 0.f, siv0 = 0.f, smiv0 = 0.f, smmiv0 = 0.f;
            float smu1 = 0.f, smu21 = 0.f, siv1 = 0.f, smiv1 = 0.f, smmiv1 = 0.f;
#pragma unroll
            for (int t = 0; t < 2; t++) {
#pragma unroll
                for (int h = 0; h < 2; h++) {
                    const int row = m0 + wm0 + t * 16 + g + h * 8;
                    float mu0 = c[0][t][j][h * 2 + 0] + bm0;
                    float mu1 = c[0][t][j][h * 2 + 1] + bm1;
                    float v0 = c[1][t][j][h * 2 + 0] + bb0;
                    float v1 = c[1][t][j][h * 2 + 1] + bb1;
                    float iv0 = __expf(-tanh_fast(v0));
                    float iv1 = __expf(-tanh_fast(v1));
                    float2 mb2 = *(const float2*)&modal_b[(size_t)row * Hdim + ncol];
                    float d0 = mu0 - mb2.x, d1 = mu1 - mb2.y;
                    accp -= d0 * d0 * 0.5f * iv0 + d1 * d1 * 0.5f * iv1;
                    smu0 += mu0; smu20 = fmaf(mu0, mu0, smu20);
                    siv0 += iv0; smiv0 = fmaf(mu0, iv0, smiv0);
                    smmiv0 = fmaf(mu0 * mu0, iv0, smmiv0);
                    smu1 += mu1; smu21 = fmaf(mu1, mu1, smu21);
                    siv1 += iv1; smiv1 = fmaf(mu1, iv1, smiv1);
                    smmiv1 = fmaf(mu1 * mu1, iv1, smmiv1);
                }
            }
            // reduce over g (lane bits 2..4)
#pragma unroll
            for (int msk = 4; msk <= 16; msk <<= 1) {
                smu0 += __shfl_xor_sync(0xffffffffu, smu0, msk);
                smu20 += __shfl_xor_sync(0xffffffffu, smu20, msk);
                siv0 += __shfl_xor_sync(0xffffffffu, siv0, msk);
                smiv0 += __shfl_xor_sync(0xffffffffu, smiv0, msk);
                smmiv0 += __shfl_xor_sync(0xffffffffu, smmiv0, msk);
                smu1 += __shfl_xor_sync(0xffffffffu, smu1, msk);
                smu21 += __shfl_xor_sync(0xffffffffu, smu21, msk);
                siv1 += __shfl_xor_sync(0xffffffffu, siv1, msk);
                smiv1 += __shfl_xor_sync(0xffffffffu, smiv1, msk);
                smmiv1 += __shfl_xor_sync(0xffffffffu, smmiv1, msk);
            }
            if (lane < 4) {
                const int cl = wn0 + j * 8 + tg * 2;
                const int mw = wid & 3;
                sOv[0 * 256 + mw * 64 + cl] = smu0;  sOv[0 * 256 + mw * 64 + cl + 1] = smu1;
                sOv[1 * 256 + mw * 64 + cl] = smu20; sOv[1 * 256 + mw * 64 + cl + 1] = smu21;
                sOv[2 * 256 + mw * 64 + cl] = siv0;  sOv[2 * 256 + mw * 64 + cl + 1] = siv1;
                sOv[3 * 256 + mw * 64 + cl] = smiv0; sOv[3 * 256 + mw * 64 + cl + 1] = smiv1;
                sOv[4 * 256 + mw * 64 + cl] = smmiv0; sOv[4 * 256 + mw * 64 + cl + 1] = smmiv1;
            }
        }
        sP[tid] = accp;
        __syncthreads();

        // per-(by,col) sums: 5 arrays x 64 cols
        for (int q = tid; q < 320; q += 256) {
            const int arr = q >> 6;
            const int cl = q & 63;
            g_colpart[arr][by][n0 + cl] =
                sOv[arr * 256 + cl] + sOv[arr * 256 + 64 + cl] +
                sOv[arr * 256 + 128 + cl] + sOv[arr * 256 + 192 + cl];
        }
        // per-tile pos reduction
        for (int s = 128; s > 0; s >>= 1) {
            if (tid < s) sP[tid] += sP[tid + s];
            __syncthreads();
        }
        if (tid == 0) g_part[tile] = sP[0];
        __syncthreads();
    }
}

// ------------- per-column neg finalize (deterministic over 64 chunks) ------------
__global__ __launch_bounds__(256) void colfinal() {
    const int col = blockIdx.x * 32 + (threadIdx.x >> 3);
    const int sub = threadIdx.x & 7;
    float s[5] = {0.f, 0.f, 0.f, 0.f, 0.f};
#pragma unroll
    for (int k = 0; k < 8; k++) {
        const int rc = sub * 8 + k;
#pragma unroll
        for (int arr = 0; arr < 5; arr++) s[arr] += g_colpart[arr][rc][col];
    }
#pragma unroll
    for (int msk = 4; msk >= 1; msk >>= 1)
#pragma unroll
        for (int arr = 0; arr < 5; arr++)
            s[arr] += __shfl_xor_sync(0xffffffffu, s[arr], msk);
    if (sub == 0) {
        const float invB = 1.0f / (float)Mdim;
        const float colmean = s[0] * invB;
        const float colsq = s[1] * invB;
        // sum_i neg(i,col) = -0.5*(colsq*Siv - 2*colmean*Smiv + Smmiv)
        g_negcol[col] = -0.5f * (colsq * s[2] - 2.0f * colmean * s[3] + s[4]);
    }
}

// ------------- final scalar reduction --------------------------------------------
__global__ __launch_bounds__(256) void final_reduce(float* __restrict__ out) {
    __shared__ float shp[256];
    __shared__ float shn[256];
    const int tid = threadIdx.x;
    float sp = 0.0f, sn = 0.0f;
    for (int i = tid; i < NTILES; i += 256) sp += g_part[i];
    for (int i = tid; i < Hdim; i += 256) sn += g_negcol[i];
    shp[tid] = sp;
    shn[tid] = sn;
    __syncthreads();
    for (int s = 128; s > 0; s >>= 1) {
        if (tid < s) { shp[tid] += shp[tid + s]; shn[tid] += shn[tid + s]; }
        __syncthreads();
    }
    if (tid == 0) {
        const float invB = 1.0f / (float)Mdim;
        out[0] = shp[0] * invB;               // lld = mean(pos_sum)
        out[1] = (shp[0] - shn[0]) * invB;    // bound = mean(pos_sum - neg_sum)
    }
}

// --------------------------------- launcher --------------------------------------
extern "C" void kernel_launch(void* const* d_in, const int* in_sizes, int n_in,
                              void* d_out, int out_size) {
    const float* modal_a = (const float*)d_in[0];
    const float* modal_b = (const float*)d_in[1];
    const float* b1m = (const float*)d_in[3];
    const float* b2m = (const float*)d_in[5];
    const float* b1v = (const float*)d_in[7];
    const float* b2v = (const float*)d_in[9];
    float* out = (float*)d_out;

    __half *ah, *wh, *hm, *hv;
    cudaGetSymbolAddress((void**)&ah, g_ah);
    cudaGetSymbolAddress((void**)&wh, g_wh);
    cudaGetSymbolAddress((void**)&hm, g_hm);
    cudaGetSymbolAddress((void**)&hv, g_hv);
    __half* w1m = wh + 0 * (size_t)Hdim * Hdim;
    __half* w1v = wh + 1 * (size_t)Hdim * Hdim;
    __half* w2m = wh + 2 * (size_t)Hdim * Hdim;
    __half* w2v = wh + 3 * (size_t)Hdim * Hdim;

    const int SMEM_L1 = PST1 * (BM + 2 * BN) * RSW * 4;          // 81920
    const int SMEM_L2 = PST2 * (2 * BM + 2 * BN) * RSW * 4;      // 92160
    cudaFuncSetAttribute((const void*)gemm_l1,
                         cudaFuncAttributeMaxDynamicSharedMemorySize, SMEM_L1);
    cudaFuncSetAttribute((const void*)gemm_l2dual,
                         cudaFuncAttributeMaxDynamicSharedMemorySize, SMEM_L2);

    pack_all<<<1184, 256>>>(modal_a, (const float*)d_in[2], (const float*)d_in[6],
                            (const float*)d_in[4], (const float*)d_in[8], ah, wh);

    // layer 1: both branches in one tile (shared A), dynamic scheduling
    gemm_l1<<<PGRID2, 256, SMEM_L1>>>(ah, w1m, w1v, b1m, b1v, hm, hv);
    // layer 2: dual GEMM (mu & v together) + fused loss statistics
    gemm_l2dual<<<PGRID2, 256, SMEM_L2>>>(hm, hv, w2m, w2v, b2m, b2v, modal_b);
    // finalize
    colfinal<<<24, 256>>>();
    final_reduce<<<1, 256>>>(out);
}

// round 15
// speedup vs baseline: 1.0654x; 1.0654x over previous
#include <cuda_runtime.h>
#include <cuda_fp16.h>
#include <cstdint>
#include <math.h>

#define Mdim 8192
#define Hdim 768
#define BM 128
#define BN 64
#define BK 32
#define RSW 20          // smem row stride in 32-bit words (40 halves)
#define NKT (Hdim / BK) // 24
#define PSTAGES 4       // cp.async pipeline depth (3 in flight)
#define NTILE_X (Hdim / BN)   // 12
#define NTILE_Y (Mdim / BM)   // 64
#define NTILES (NTILE_X * NTILE_Y)  // 768
#define PGRID 444       // persistent grid: 3 CTAs/SM * 148 (L2 kernels)
#define PGRID2 296      // persistent grid: 2 CTAs/SM * 148 (L1 dual kernel)

// ---------------- scratch (static device globals; no allocation) ----------------
__device__ __half g_ah[Mdim * Hdim];     // fp16 modal_a
__device__ __half g_wh[4][Hdim * Hdim];  // fp16 W1m, W1v, W2m, W2v
__device__ __half g_hm[Mdim * Hdim];     // fp16 tanh(layer1m)
__device__ __half g_hv[Mdim * Hdim];     // fp16 tanh(layer1v)
__device__ __half g_muh[Mdim * Hdim];    // fp16 mu
__device__ float g_colpart[2][NTILE_Y][Hdim];
__device__ float g_colmean[Hdim];
__device__ float g_colsq[Hdim];
__device__ float g_part[NTILES * 2];     // per-tile loss partials
__device__ int g_ctr[4];                 // work-stealing counters

// ---------------------------- helpers -------------------------------------------
__device__ __forceinline__ uint32_t smem_u32(const void* p) {
    uint32_t a;
    asm("{ .reg .u64 t; cvta.to.shared.u64 t, %1; cvt.u32.u64 %0, t; }"
        : "=r"(a) : "l"(p));
    return a;
}
__device__ __forceinline__ float tanh_fast(float x) {
    float y;
    asm("tanh.approx.f32 %0, %1;" : "=f"(y) : "f"(x));
    return y;
}
#define LDSM_X4(r0, r1, r2, r3, addr) \
    asm volatile("ldmatrix.sync.aligned.m8n8.x4.shared.b16 {%0,%1,%2,%3}, [%4];" \
        : "=r"(r0), "=r"(r1), "=r"(r2), "=r"(r3) : "r"(addr))
#define MMA16816(c0, c1, c2, c3, a0, a1, a2, a3, b0, b1) \
    asm volatile( \
        "mma.sync.aligned.m16n8k16.row.col.f32.f16.f16.f32 " \
        "{%0,%1,%2,%3}, {%4,%5,%6,%7}, {%8,%9}, {%0,%1,%2,%3};" \
        : "+f"(c0), "+f"(c1), "+f"(c2), "+f"(c3) \
        : "r"(a0), "r"(a1), "r"(a2), "r"(a3), "r"(b0), "r"(b1))

// -------------------- pack: modal_a + all 4 weights, one launch ------------------
// 8 floats per iter -> one 16B store (full-width STG.128).
__global__ __launch_bounds__(256) void pack_all(
    const float* __restrict__ a,
    const float* __restrict__ w0, const float* __restrict__ w1,
    const float* __restrict__ w2, const float* __restrict__ w3,
    __half* __restrict__ ah, __half* __restrict__ wh) {
    if (blockIdx.x == 0 && threadIdx.x < 4) g_ctr[threadIdx.x] = 0;  // reset schedulers
    const int na = Mdim * Hdim / 8;
    const int nw = Hdim * Hdim / 8;
    const int total = na + 4 * nw;
    for (int i = blockIdx.x * 256 + threadIdx.x; i < total; i += gridDim.x * 256) {
        const float* src;
        __half* dst;
        int idx;
        if (i < na) { src = a; dst = ah; idx = i; }
        else {
            int r = i - na;
            int wsel = r / nw;
            idx = r - wsel * nw;
            src = (wsel == 0) ? w0 : (wsel == 1) ? w1 : (wsel == 2) ? w2 : w3;
            dst = wh + (size_t)wsel * Hdim * Hdim;
        }
        float4 v0 = ((const float4*)src)[idx * 2];
        float4 v1 = ((const float4*)src)[idx * 2 + 1];
        __half2 h0 = __floats2half2_rn(v0.x, v0.y);
        __half2 h1 = __floats2half2_rn(v0.z, v0.w);
        __half2 h2 = __floats2half2_rn(v1.x, v1.y);
        __half2 h3 = __floats2half2_rn(v1.z, v1.w);
        *(uint4*)(dst + (size_t)idx * 8) =
            make_uint4(*(uint32_t*)&h0, *(uint32_t*)&h1,
                       *(uint32_t*)&h2, *(uint32_t*)&h3);
    }
}

// ---------------- layer-1 dual-branch GEMM: one A tile, two B tiles --------------
__global__ __launch_bounds__(256, 2) void gemm_l1(
    const __half* __restrict__ A,
    const __half* __restrict__ W0, const __half* __restrict__ W1,
    const float* __restrict__ bias0, const float* __restrict__ bias1,
    __half* __restrict__ H0, __half* __restrict__ H1)
{
    extern __shared__ uint32_t sm[];
    __shared__ int s_tile;
    const uint32_t sA = smem_u32(sm);
    const uint32_t sB0 = sA + PSTAGES * BM * RSW * 4;
    const uint32_t sB1 = sB0 + PSTAGES * BN * RSW * 4;

    const int tid = threadIdx.x;
    const int wid = tid >> 5, lane = tid & 31;
    const int g = lane >> 2, tg = lane & 3;
    const int wm0 = (wid & 3) * 32;
    const int wn0 = (wid >> 2) * 32;

    const int lrow = tid >> 2;
    const int lc = tid & 3;
    const uint32_t dab = sA + (uint32_t)(lrow * RSW + lc * 4) * 4;
    const uint32_t db0 = sB0 + (uint32_t)(lrow * RSW + lc * 4) * 4;
    const uint32_t db1 = sB1 + (uint32_t)(lrow * RSW + lc * 4) * 4;
    const uint32_t rowstep = 64 * RSW * 4;
    const uint32_t abufstep = BM * RSW * 4;
    const uint32_t bbufstep = BN * RSW * 4;

    const int mi = lane >> 3, mr = lane & 7;
    uint32_t aoff[2];
#pragma unroll
    for (int t = 0; t < 2; t++)
        aoff[t] = (uint32_t)(((wm0 + t * 16 + (mi & 1) * 8 + mr) * RSW + (mi >> 1) * 4) * 4);
    uint32_t boff[2];
#pragma unroll
    for (int jp = 0; jp < 2; jp++)
        boff[jp] = (uint32_t)(((wn0 + (jp * 2 + (mi >> 1)) * 8 + mr) * RSW + (mi & 1) * 4) * 4);

    while (true) {
        if (tid == 0) s_tile = atomicAdd(&g_ctr[0], 1);
        __syncthreads();
        const int tile = s_tile;
        if (tile >= NTILES) break;
        __syncthreads();

        const int by = tile / NTILE_X;
        const int bx = tile - by * NTILE_X;
        const int m0 = by * BM;
        const int n0 = bx * BN;

        const __half* agb = A + (size_t)(m0 + lrow) * Hdim + lc * 8;
        const __half* b0gb = W0 + (size_t)(n0 + lrow) * Hdim + lc * 8;
        const __half* b1gb = W1 + (size_t)(n0 + lrow) * Hdim + lc * 8;

        float c[2][2][4][4];
#pragma unroll
        for (int br = 0; br < 2; br++)
#pragma unroll
            for (int t = 0; t < 2; t++)
#pragma unroll
                for (int j = 0; j < 4; j++)
#pragma unroll
                    for (int q = 0; q < 4; q++) c[br][t][j][q] = 0.0f;

#define PREFETCH(kt) do { \
    const __half* _ag = agb + (kt) * BK; \
    uint32_t _da = dab + ((kt) % PSTAGES) * abufstep; \
    asm volatile("cp.async.cg.shared.global [%0], [%1], 16;" \
        :: "r"(_da), "l"(_ag) : "memory"); \
    asm volatile("cp.async.cg.shared.global [%0], [%1], 16;" \
        :: "r"(_da + rowstep), "l"(_ag + (size_t)64 * Hdim) : "memory"); \
    asm volatile("cp.async.cg.shared.global [%0], [%1], 16;" \
        :: "r"(db0 + ((kt) % PSTAGES) * bbufstep), "l"(b0gb + (kt) * BK) : "memory"); \
    asm volatile("cp.async.cg.shared.global [%0], [%1], 16;" \
        :: "r"(db1 + ((kt) % PSTAGES) * bbufstep), "l"(b1gb + (kt) * BK) : "memory"); \
    asm volatile("cp.async.commit_group;" ::: "memory"); \
} while (0)

        PREFETCH(0);
        PREFETCH(1);
        PREFETCH(2);

        for (int kt = 0; kt < NKT; kt++) {
            asm volatile("cp.async.wait_group 2;" ::: "memory");
            __syncthreads();

            if (kt + 3 < NKT) PREFETCH(kt + 3);
            else asm volatile("cp.async.commit_group;" ::: "memory");

            const uint32_t stA = sA + (kt % PSTAGES) * abufstep;
            const uint32_t stB0 = sB0 + (kt % PSTAGES) * bbufstep;
            const uint32_t stB1 = sB1 + (kt % PSTAGES) * bbufstep;
#pragma unroll
            for (int ks = 0; ks < 2; ks++) {
                const uint32_t ko = ks * 32;
                uint32_t a[2][4];
#pragma unroll
                for (int t = 0; t < 2; t++)
                    LDSM_X4(a[t][0], a[t][1], a[t][2], a[t][3], stA + aoff[t] + ko);
#pragma unroll
                for (int jp = 0; jp < 2; jp++) {
                    uint32_t b[4];
                    LDSM_X4(b[0], b[1], b[2], b[3], stB0 + boff[jp] + ko);
#pragma unroll
                    for (int t = 0; t < 2; t++) {
                        MMA16816(c[0][t][jp*2][0], c[0][t][jp*2][1], c[0][t][jp*2][2], c[0][t][jp*2][3],
                                 a[t][0], a[t][1], a[t][2], a[t][3], b[0], b[1]);
                        MMA16816(c[0][t][jp*2+1][0], c[0][t][jp*2+1][1], c[0][t][jp*2+1][2], c[0][t][jp*2+1][3],
                                 a[t][0], a[t][1], a[t][2], a[t][3], b[2], b[3]);
                    }
                }
#pragma unroll
                for (int jp = 0; jp < 2; jp++) {
                    uint32_t b[4];
                    LDSM_X4(b[0], b[1], b[2], b[3], stB1 + boff[jp] + ko);
#pragma unroll
                    for (int t = 0; t < 2; t++) {
                        MMA16816(c[1][t][jp*2][0], c[1][t][jp*2][1], c[1][t][jp*2][2], c[1][t][jp*2][3],
                                 a[t][0], a[t][1], a[t][2], a[t][3], b[0], b[1]);
                        MMA16816(c[1][t][jp*2+1][0], c[1][t][jp*2+1][1], c[1][t][jp*2+1][2], c[1][t][jp*2+1][3],
                                 a[t][0], a[t][1], a[t][2], a[t][3], b[2], b[3]);
                    }
                }
            }
        }
#undef PREFETCH

#pragma unroll
        for (int br = 0; br < 2; br++) {
            const float* bias = br ? bias1 : bias0;
            __half* Ch = br ? H1 : H0;
#pragma unroll
            for (int j = 0; j < 4; j++) {
                const int ncol = n0 + wn0 + j * 8 + tg * 2;
                const float bv0 = bias[ncol];
                const float bv1 = bias[ncol + 1];
#pragma unroll
                for (int t = 0; t < 2; t++) {
#pragma unroll
                    for (int h = 0; h < 2; h++) {
                        const int row = m0 + wm0 + t * 16 + g + h * 8;
                        float v0 = c[br][t][j][h * 2 + 0] + bv0;
                        float v1 = c[br][t][j][h * 2 + 1] + bv1;
                        __half2 hv = __floats2half2_rn(tanh_fast(v0), tanh_fast(v1));
                        *(__half2*)&Ch[(size_t)row * Hdim + ncol] = hv;
                    }
                }
            }
        }
        __syncthreads();
    }
}

// -------------------- persistent fp16 GEMM, layer-2 epilogues --------------------
// KIND 1: layer-2 mu; fp16 store + column partials (counter 1)
// KIND 2: layer-2 iv + fused final loss epilogue, per-tile partials (counter 2)
template <int KIND>
__global__ __launch_bounds__(256, 3) void gemm_pers(
    const __half* __restrict__ A0,
    const __half* __restrict__ W0,
    const float* __restrict__ bias0,
    __half* __restrict__ Pmu,
    const float* __restrict__ modal_b)
{
    extern __shared__ uint32_t sm[];
    __shared__ int s_tile;
    const uint32_t sA = smem_u32(sm);
    const uint32_t sB = sA + PSTAGES * BM * RSW * 4;

    const int tid = threadIdx.x;
    const int wid = tid >> 5, lane = tid & 31;
    const int g = lane >> 2, tg = lane & 3;
    const int wm0 = (wid & 3) * 32;
    const int wn0 = (wid >> 2) * 32;

    const int lrow = tid >> 2;
    const int lc = tid & 3;
    const uint32_t dab = sA + (uint32_t)(lrow * RSW + lc * 4) * 4;
    const uint32_t dbb = sB + (uint32_t)(lrow * RSW + lc * 4) * 4;
    const uint32_t rowstep = 64 * RSW * 4;
    const uint32_t abufstep = BM * RSW * 4;
    const uint32_t bbufstep = BN * RSW * 4;

    const int mi = lane >> 3, mr = lane & 7;
    uint32_t aoff[2];
#pragma unroll
    for (int t = 0; t < 2; t++)
        aoff[t] = (uint32_t)(((wm0 + t * 16 + (mi & 1) * 8 + mr) * RSW + (mi >> 1) * 4) * 4);
    uint32_t boff[2];
#pragma unroll
    for (int jp = 0; jp < 2; jp++)
        boff[jp] = (uint32_t)(((wn0 + (jp * 2 + (mi >> 1)) * 8 + mr) * RSW + (mi & 1) * 4) * 4);

    float* sS = (float*)sm;
    float* sQ = sS + 256;

    while (true) {
        if (tid == 0) s_tile = atomicAdd(&g_ctr[KIND], 1);
        __syncthreads();
        const int tile = s_tile;
        if (tile >= NTILES) break;
        __syncthreads();

        const int by = tile / NTILE_X;
        const int bx = tile - by * NTILE_X;
        const int m0 = by * BM;
        const int n0 = bx * BN;

        const __half* agb = A0 + (size_t)(m0 + lrow) * Hdim + lc * 8;
        const __half* bgb = W0 + (size_t)(n0 + lrow) * Hdim + lc * 8;

        float c[2][4][4];
#pragma unroll
        for (int t = 0; t < 2; t++)
#pragma unroll
            for (int j = 0; j < 4; j++)
#pragma unroll
                for (int q = 0; q < 4; q++) c[t][j][q] = 0.0f;

#define PREFETCH(kt) do { \
    const __half* _ag = agb + (kt) * BK; \
    const __half* _bg = bgb + (kt) * BK; \
    uint32_t _da = dab + ((kt) % PSTAGES) * abufstep; \
    uint32_t _db = dbb + ((kt) % PSTAGES) * bbufstep; \
    asm volatile("cp.async.cg.shared.global [%0], [%1], 16;" \
        :: "r"(_da), "l"(_ag) : "memory"); \
    asm volatile("cp.async.cg.shared.global [%0], [%1], 16;" \
        :: "r"(_da + rowstep), "l"(_ag + (size_t)64 * Hdim) : "memory"); \
    if (lrow < BN) \
        asm volatile("cp.async.cg.shared.global [%0], [%1], 16;" \
            :: "r"(_db), "l"(_bg) : "memory"); \
    asm volatile("cp.async.commit_group;" ::: "memory"); \
} while (0)

        PREFETCH(0);
        PREFETCH(1);
        PREFETCH(2);

        for (int kt = 0; kt < NKT; kt++) {
            asm volatile("cp.async.wait_group 2;" ::: "memory");
            __syncthreads();

            if (kt + 3 < NKT) PREFETCH(kt + 3);
            else asm volatile("cp.async.commit_group;" ::: "memory");

            const uint32_t stA = sA + (kt % PSTAGES) * abufstep;
            const uint32_t stB = sB + (kt % PSTAGES) * bbufstep;
#pragma unroll
            for (int ks = 0; ks < 2; ks++) {
                const uint32_t ko = ks * 32;
                uint32_t a[2][4];
#pragma unroll
                for (int t = 0; t < 2; t++)
                    LDSM_X4(a[t][0], a[t][1], a[t][2], a[t][3], stA + aoff[t] + ko);
#pragma unroll
                for (int jp = 0; jp < 2; jp++) {
                    uint32_t b[4];
                    LDSM_X4(b[0], b[1], b[2], b[3], stB + boff[jp] + ko);
#pragma unroll
                    for (int t = 0; t < 2; t++) {
                        MMA16816(c[t][jp*2][0], c[t][jp*2][1], c[t][jp*2][2], c[t][jp*2][3],
                                 a[t][0], a[t][1], a[t][2], a[t][3], b[0], b[1]);
                        MMA16816(c[t][jp*2+1][0], c[t][jp*2+1][1], c[t][jp*2+1][2], c[t][jp*2+1][3],
                                 a[t][0], a[t][1], a[t][2], a[t][3], b[2], b[3]);
                    }
                }
            }
        }
#undef PREFETCH

        // -------- epilogue --------
        float accp = 0.0f, accd = 0.0f;   // KIND 2: per-tile partials
        __syncthreads();                  // smem overlay safe (all warps past k-loop)
#pragma unroll
        for (int j = 0; j < 4; j++) {
            const int ncol = n0 + wn0 + j * 8 + tg * 2;
            const float bv0 = bias0[ncol];
            const float bv1 = bias0[ncol + 1];
            float s0 = 0.f, s1 = 0.f, q0 = 0.f, q1 = 0.f;
            float cm0, cm1, cq0, cq1;
            if (KIND == 2) {
                float2 cm = *(const float2*)&g_colmean[ncol];
                float2 cq = *(const float2*)&g_colsq[ncol];
                cm0 = cm.x; cm1 = cm.y; cq0 = cq.x; cq1 = cq.y;
            }
#pragma unroll
            for (int t = 0; t < 2; t++) {
#pragma unroll
                for (int h = 0; h < 2; h++) {
                    const int row = m0 + wm0 + t * 16 + g + h * 8;
                    float v0 = c[t][j][h * 2 + 0] + bv0;
                    float v1 = c[t][j][h * 2 + 1] + bv1;
                    if (KIND == 1) {
                        __half2 mh = __floats2half2_rn(v0, v1);
                        *(__half2*)&Pmu[(size_t)row * Hdim + ncol] = mh;
                        s0 += v0; q0 = fmaf(v0, v0, q0);
                        s1 += v1; q1 = fmaf(v1, v1, q1);
                    } else {
                        float iv0 = __expf(-tanhf(v0));
                        float iv1 = __expf(-tanhf(v1));
                        __half2 mh = *(const __half2*)&Pmu[(size_t)row * Hdim + ncol];
                        float2 mu2 = __half22float2(mh);
                        float2 mb2 = *(const float2*)&modal_b[(size_t)row * Hdim + ncol];
                        float d0 = mu2.x - mb2.x, d1 = mu2.y - mb2.y;
                        float pos0 = -d0 * d0 * 0.5f * iv0;
                        float pos1 = -d1 * d1 * 0.5f * iv1;
                        float pr0 = cq0 - 2.0f * mu2.x * cm0 + mu2.x * mu2.x;
                        float pr1 = cq1 - 2.0f * mu2.y * cm1 + mu2.y * mu2.y;
                        float neg0 = -pr0 * 0.5f * iv0;
                        float neg1 = -pr1 * 0.5f * iv1;
                        accp += pos0 + pos1;
                        accd += (pos0 - neg0) + (pos1 - neg1);
                    }
                }
            }
            if (KIND == 1) {
#pragma unroll
                for (int msk = 4; msk <= 16; msk <<= 1) {
                    s0 += __shfl_xor_sync(0xffffffffu, s0, msk);
                    q0 += __shfl_xor_sync(0xffffffffu, q0, msk);
                    s1 += __shfl_xor_sync(0xffffffffu, s1, msk);
                    q1 += __shfl_xor_sync(0xffffffffu, q1, msk);
                }
                if (lane < 4) {
                    const int cl = wn0 + j * 8 + tg * 2;
                    const int mw = wid & 3;
                    sS[mw * 64 + cl] = s0; sQ[mw * 64 + cl] = q0;
                    sS[mw * 64 + cl + 1] = s1; sQ[mw * 64 + cl + 1] = q1;
                }
            }
        }
        if (KIND == 1) {
            __syncthreads();
            if (tid < 64) {
                const int cl = tid;
                g_colpart[0][by][n0 + cl] =
                    sS[cl] + sS[64 + cl] + sS[128 + cl] + sS[192 + cl];
            } else if (tid < 128) {
                const int cl = tid - 64;
                g_colpart[1][by][n0 + cl] =
                    sQ[cl] + sQ[64 + cl] + sQ[128 + cl] + sQ[192 + cl];
            }
        } else {
            // per-tile deterministic loss reduction
            sS[tid] = accp;
            sQ[tid] = accd;
            __syncthreads();
            for (int s = 128; s > 0; s >>= 1) {
                if (tid < s) { sS[tid] += sS[tid + s]; sQ[tid] += sQ[tid + s]; }
                __syncthreads();
            }
            if (tid == 0) {
                g_part[tile * 2 + 0] = sS[0];
                g_part[tile * 2 + 1] = sQ[0];
            }
        }
        __syncthreads();
    }
}

// ------------- column moments: warp-per-column over 64 chunks --------------------
// 96 blocks x 8 warps = 768 columns; each lane sums 2 chunks, shfl-reduce 32 lanes.
__global__ __launch_bounds__(256) void col_moments_s2() {
    const int wid = threadIdx.x >> 5, lane = threadIdx.x & 31;
    const int col = blockIdx.x * 8 + wid;
    float s = g_colpart[0][lane][col] + g_colpart[0][lane + 32][col];
    float q = g_colpart[1][lane][col] + g_colpart[1][lane + 32][col];
#pragma unroll
    for (int msk = 16; msk >= 1; msk >>= 1) {
        s += __shfl_xor_sync(0xffffffffu, s, msk);
        q += __shfl_xor_sync(0xffffffffu, q, msk);
    }
    if (lane == 0) {
        const float invB = 1.0f / (float)Mdim;
        g_colmean[col] = s * invB;
        g_colsq[col] = q * invB;
    }
}

__global__ __launch_bounds__(256) void final_reduce(float* __restrict__ out, int nblocks) {
    __shared__ float shp[256];
    __shared__ float shd[256];
    const int tid = threadIdx.x;
    float sp = 0.0f, sd = 0.0f;
    for (int i = tid; i < nblocks; i += 256) {
        sp += g_part[i * 2 + 0];
        sd += g_part[i * 2 + 1];
    }
    shp[tid] = sp;
    shd[tid] = sd;
    __syncthreads();
    for (int s = 128; s > 0; s >>= 1) {
        if (tid < s) { shp[tid] += shp[tid + s]; shd[tid] += shd[tid + s]; }
        __syncthreads();
    }
    if (tid == 0) {
        const float invB = 1.0f / (float)Mdim;
        out[0] = shp[0] * invB;
        out[1] = shd[0] * invB;
    }
}

// --------------------------------- launcher --------------------------------------
extern "C" void kernel_launch(void* const* d_in, const int* in_sizes, int n_in,
                              void* d_out, int out_size) {
    const float* modal_a = (const float*)d_in[0];
    const float* modal_b = (const float*)d_in[1];
    const float* b1m = (const float*)d_in[3];
    const float* b2m = (const float*)d_in[5];
    const float* b1v = (const float*)d_in[7];
    const float* b2v = (const float*)d_in[9];
    float* out = (float*)d_out;

    __half *ah, *wh, *hm, *hv, *muh;
    cudaGetSymbolAddress((void**)&ah, g_ah);
    cudaGetSymbolAddress((void**)&wh, g_wh);
    cudaGetSymbolAddress((void**)&hm, g_hm);
    cudaGetSymbolAddress((void**)&hv, g_hv);
    cudaGetSymbolAddress((void**)&muh, g_muh);
    __half* w1m = wh + 0 * (size_t)Hdim * Hdim;
    __half* w1v = wh + 1 * (size_t)Hdim * Hdim;
    __half* w2m = wh + 2 * (size_t)Hdim * Hdim;
    __half* w2v = wh + 3 * (size_t)Hdim * Hdim;

    const int SMEM_L1 = PSTAGES * (BM + 2 * BN) * RSW * 4;  // 81920
    const int SMEM_L2 = PSTAGES * (BM + BN) * RSW * 4;      // 61440
    cudaFuncSetAttribute((const void*)gemm_l1,
                         cudaFuncAttributeMaxDynamicSharedMemorySize, SMEM_L1);
    cudaFuncSetAttribute((const void*)gemm_pers<1>,
                         cudaFuncAttributeMaxDynamicSharedMemorySize, SMEM_L2);
    cudaFuncSetAttribute((const void*)gemm_pers<2>,
                         cudaFuncAttributeMaxDynamicSharedMemorySize, SMEM_L2);

    pack_all<<<1184, 256>>>(modal_a, (const float*)d_in[2], (const float*)d_in[6],
                            (const float*)d_in[4], (const float*)d_in[8], ah, wh);

    // layer 1: both branches in one tile (shared A), dynamic scheduling
    gemm_l1<<<PGRID2, 256, SMEM_L1>>>(ah, w1m, w1v, b1m, b1v, hm, hv);
    // layer 2 mu: fp16 store + column partials
    gemm_pers<1><<<PGRID, 256, SMEM_L2>>>(hm, w2m, b2m, muh, nullptr);
    col_moments_s2<<<96, 256>>>();
    // layer 2 iv + fused final loss epilogue (per-tile partials)
    gemm_pers<2><<<PGRID, 256, SMEM_L2>>>(hv, w2v, b2v, muh, modal_b);
    final_reduce<<<1, 256>>>(out, NTILES);
}